// round 7
// baseline (speedup 1.0000x reference)
#include <cuda_runtime.h>
#include <cstdint>

#define HH 128
#define WW 128
#define BB 8
#define NCH 32            // 32 k-chunks; each = 8 input channels x 4 branches = 32 y-channels

// ---- smem byte layout (per CTA) ----
#define AB_OFF 0                      // 2 x 36864 : A tf32 [256 m][36 words] (stride 144B)
#define AB_SZ  36864
#define YB_OFF 73728                  // 2 x 17408 : Y pair buffer [64 k][68 words] (stride 272B)
#define YB_SZ  17408
#define SMEM_BYTES 108544

// wproj pre-converted to tf32: [chunk(32)][m(256)][k(32)] u32
__device__ uint32_t g_A_tf32[32 * 256 * 32];
// depthwise weights packed: [ch(256)][conv(4: h1,h2,v1,v2)][12 floats (9 + pad)]
__device__ float g_dw[256 * 4 * 12];

// ================= helpers =================
__device__ __forceinline__ uint32_t smem_u32(const void* p) {
    uint32_t a;
    asm("{ .reg .u64 t; cvta.to.shared.u64 t, %1; cvt.u32.u64 %0, t; }" : "=r"(a) : "l"(p));
    return a;
}
__device__ __forceinline__ void cpa16(uint32_t dst, const void* src) {
    unsigned long long g = (unsigned long long)__cvta_generic_to_global((void*)src);
    asm volatile("cp.async.cg.shared.global [%0], [%1], 16;" :: "r"(dst), "l"(g));
}
__device__ __forceinline__ uint32_t f2tf32(float v) {
    uint32_t u;
    asm("cvt.rna.tf32.f32 %0, %1;" : "=r"(u) : "f"(v));
    return u;
}
__device__ __forceinline__ void ldsm4(uint32_t* r, uint32_t addr) {
    asm volatile("ldmatrix.sync.aligned.m8n8.x4.shared.b16 {%0,%1,%2,%3}, [%4];"
        : "=r"(r[0]), "=r"(r[1]), "=r"(r[2]), "=r"(r[3]) : "r"(addr));
}
__device__ __forceinline__ void mma_tf32(float* d, const uint32_t* a, const uint32_t* b) {
    asm volatile("mma.sync.aligned.m16n8k8.row.col.f32.tf32.tf32.f32 "
        "{%0,%1,%2,%3}, {%4,%5,%6,%7}, {%8,%9}, {%0,%1,%2,%3};"
        : "+f"(d[0]), "+f"(d[1]), "+f"(d[2]), "+f"(d[3])
        : "r"(a[0]), "r"(a[1]), "r"(a[2]), "r"(a[3]), "r"(b[0]), "r"(b[1]));
}

// ================= prep: wproj -> tf32, dw weights -> packed =================
__global__ void se_prep(const float* __restrict__ wproj,
                        const float* __restrict__ wh1, const float* __restrict__ wh2,
                        const float* __restrict__ wv1, const float* __restrict__ wv2)
{
    int idx = blockIdx.x * 256 + threadIdx.x;   // 262144
    int k = idx & 31;
    int m = (idx >> 5) & 255;
    int c = idx >> 13;
    int br = k >> 3, lc = k & 7;
    float v = wproj[m * 1024 + br * 256 + c * 8 + lc];
    g_A_tf32[(c * 256 + m) * 32 + k] = f2tf32(v);

    if (blockIdx.x == 0) {
        for (int i = threadIdx.x; i < 9216; i += 256) {
            int ch = i / 36, r = i - ch * 36;
            int conv = r / 9, kk = r - conv * 9;
            const float* p = (conv == 0) ? wh1 : (conv == 1) ? wh2 : (conv == 2) ? wv1 : wv2;
            g_dw[(ch * 4 + conv) * 12 + kk] = p[ch * 9 + kk];
        }
    }
}

// ================= main =================
__global__ __launch_bounds__(256, 2)
void se_main(const float* __restrict__ x, float* __restrict__ out)
{
    extern __shared__ char smc[];
    const uint32_t sb = smem_u32(smc);
    const int half = blockIdx.x, h = blockIdx.y, b = blockIdx.z;
    const int t = threadIdx.x, lane = t & 31, wid = t >> 5;
    const int wm = (wid & 3) * 64;       // output-channel tile base (M)
    const int wn = (wid >> 2) * 32;      // pixel tile base within 64-px half (N)

    // depthwise mapping: 16 pixel-groups x 16 channels (one pair = 2 chunks)
    const int ng = t & 15, ch = t >> 4;           // ch 0..15
    const int cs = ch >> 3, lch = ch & 7;         // chunk-within-pair, local channel
    const int p0 = half * 64 + ng * 4;            // global pixel base (4 px)
    const int n0 = ng * 4;                        // local pixel base

    const float* xb = x + (long)b * 256 * HH * WW;

    // ---- A prefetch: chunk c -> smem buffer dbuf ----
    auto pa = [&](int c, int dbuf) {
        #pragma unroll
        for (int i = 0; i < 8; ++i) {
            int idx = t + i * 256;           // 0..2047
            int m = idx >> 3, q = idx & 7;
            cpa16(sb + AB_OFF + (uint32_t)(dbuf * AB_SZ + m * 144 + q * 16),
                  &g_A_tf32[(c * 256 + m) * 32 + q * 4]);
        }
    };

    // ---- depthwise V (wv1, wv2) for pair pr -> Y[ybuf] rows 16..31 / 48..63 ----
    auto dwV = [&](int pr, int ybuf) {
        uint32_t* Yw = (uint32_t*)(smc + YB_OFF + ybuf * YB_SZ);
        const int gch = (2 * pr + cs) * 8 + lch;
        const float* xch = xb + (long)gch * HH * WW;
        const float* wp = g_dw + (gch * 4 + 2) * 12;
        float4 wA0 = *(const float4*)(wp), wA1 = *(const float4*)(wp + 4);
        float  wA8 = wp[8];
        float4 wB0 = *(const float4*)(wp + 12), wB1 = *(const float4*)(wp + 16);
        float  wB8 = wp[20];
        const float wa[9] = {wA0.x, wA0.y, wA0.z, wA0.w, wA1.x, wA1.y, wA1.z, wA1.w, wA8};
        const float wbv[9] = {wB0.x, wB0.y, wB0.z, wB0.w, wB1.x, wB1.y, wB1.z, wB1.w, wB8};
        float a0 = 0.f, a1 = 0.f, a2 = 0.f, a3 = 0.f;
        float b0 = 0.f, b1 = 0.f, b2 = 0.f, b3 = 0.f;
        #pragma unroll
        for (int r = 0; r < 9; ++r) {
            const int hh = h + r - 4;
            if ((unsigned)hh < 128u) {
                const float4 v = *(const float4*)(xch + hh * WW + p0);
                a0 = fmaf(wa[r], v.x, a0); b0 = fmaf(wbv[r], v.x, b0);
                a1 = fmaf(wa[r], v.y, a1); b1 = fmaf(wbv[r], v.y, b1);
                a2 = fmaf(wa[r], v.z, a2); b2 = fmaf(wbv[r], v.z, b2);
                a3 = fmaf(wa[r], v.w, a3); b3 = fmaf(wbv[r], v.w, b3);
            }
        }
        uint4 s0, s1;
        s0.x = f2tf32(a0); s0.y = f2tf32(a1); s0.z = f2tf32(a2); s0.w = f2tf32(a3);
        s1.x = f2tf32(b0); s1.y = f2tf32(b1); s1.z = f2tf32(b2); s1.w = f2tf32(b3);
        *(uint4*)(Yw + (cs * 32 + 16 + lch) * 68 + n0) = s0;
        *(uint4*)(Yw + (cs * 32 + 24 + lch) * 68 + n0) = s1;
    };

    // ---- depthwise H (wh1, wh2) for pair pr -> Y[ybuf] rows 0..15 / 32..47 ----
    auto dwH = [&](int pr, int ybuf) {
        uint32_t* Yw = (uint32_t*)(smc + YB_OFF + ybuf * YB_SZ);
        const int gch = (2 * pr + cs) * 8 + lch;
        const float* xr = xb + (long)gch * HH * WW + h * WW;
        const float* wp = g_dw + (gch * 4 + 0) * 12;
        float4 wA0 = *(const float4*)(wp), wA1 = *(const float4*)(wp + 4);
        float  wA8 = wp[8];
        float4 wB0 = *(const float4*)(wp + 12), wB1 = *(const float4*)(wp + 16);
        float  wB8 = wp[20];
        const float wa[9] = {wA0.x, wA0.y, wA0.z, wA0.w, wA1.x, wA1.y, wA1.z, wA1.w, wA8};
        const float wbv[9] = {wB0.x, wB0.y, wB0.z, wB0.w, wB1.x, wB1.y, wB1.z, wB1.w, wB8};
        float xv[12];
        if (p0 >= 4) {
            float4 v = *(const float4*)(xr + p0 - 4);
            xv[0] = v.x; xv[1] = v.y; xv[2] = v.z; xv[3] = v.w;
        } else { xv[0] = xv[1] = xv[2] = xv[3] = 0.f; }
        {
            float4 v = *(const float4*)(xr + p0);
            xv[4] = v.x; xv[5] = v.y; xv[6] = v.z; xv[7] = v.w;
        }
        if (p0 + 7 < 128) {
            float4 v = *(const float4*)(xr + p0 + 4);
            xv[8] = v.x; xv[9] = v.y; xv[10] = v.z; xv[11] = v.w;
        } else { xv[8] = xv[9] = xv[10] = xv[11] = 0.f; }
        float a0 = 0.f, a1 = 0.f, a2 = 0.f, a3 = 0.f;
        float b0 = 0.f, b1 = 0.f, b2 = 0.f, b3 = 0.f;
        #pragma unroll
        for (int k = 0; k < 9; ++k) {
            a0 = fmaf(wa[k], xv[k],     a0); b0 = fmaf(wbv[k], xv[k],     b0);
            a1 = fmaf(wa[k], xv[k + 1], a1); b1 = fmaf(wbv[k], xv[k + 1], b1);
            a2 = fmaf(wa[k], xv[k + 2], a2); b2 = fmaf(wbv[k], xv[k + 2], b2);
            a3 = fmaf(wa[k], xv[k + 3], a3); b3 = fmaf(wbv[k], xv[k + 3], b3);
        }
        uint4 s0, s1;
        s0.x = f2tf32(a0); s0.y = f2tf32(a1); s0.z = f2tf32(a2); s0.w = f2tf32(a3);
        s1.x = f2tf32(b0); s1.y = f2tf32(b1); s1.z = f2tf32(b2); s1.w = f2tf32(b3);
        *(uint4*)(Yw + (cs * 32 + lch) * 68 + n0)     = s0;
        *(uint4*)(Yw + (cs * 32 + 8 + lch) * 68 + n0) = s1;
    };

    // ---- prologue: A(0) + full dw for pair 0 ----
    pa(0, 0);
    asm volatile("cp.async.commit_group;" ::: "memory");
    dwV(0, 0);
    dwH(0, 0);
    asm volatile("cp.async.wait_group 0;" ::: "memory");
    __syncthreads();

    float acc[4][4][4];
    #pragma unroll
    for (int i = 0; i < 4; ++i)
        #pragma unroll
        for (int j = 0; j < 4; ++j)
            #pragma unroll
            for (int e = 0; e < 4; ++e) acc[i][j][e] = 0.f;

    const int fr = lane >> 2, fq = lane & 3;
    const uint32_t aLane = (uint32_t)(((lane & 7) + ((lane >> 3) & 1) * 8) * 144 + ((lane >> 4) << 4));

    // ---- main loop: one barrier per chunk; V-dw on even c, H-dw on odd c ----
    for (int c = 0; c < NCH; ++c) {
        const int buf = c & 1;
        if (c + 1 < NCH) {
            pa(c + 1, buf ^ 1);
            asm volatile("cp.async.commit_group;" ::: "memory");
        }
        const int pr = (c >> 1) + 1;          // pair being produced
        if (pr < 16) {
            if ((c & 1) == 0) dwV(pr, pr & 1);
            else              dwH(pr, pr & 1);
        }

        {   // MMA chunk c: tf32, K=32 in 4 ksteps of 8; A via ldmatrix, B scalar
            const uint32_t abase = sb + AB_OFF + (uint32_t)(buf * AB_SZ) + (uint32_t)(wm * 144) + aLane;
            const uint32_t* Yp = (const uint32_t*)(smc + YB_OFF + ((c >> 1) & 1) * YB_SZ);
            const int kbase = (c & 1) * 32;
            #pragma unroll
            for (int ks = 0; ks < 4; ++ks) {
                const int k0 = ks * 8;
                uint32_t a[4][4];
                #pragma unroll
                for (int mt = 0; mt < 4; ++mt)
                    ldsm4(a[mt], abase + (uint32_t)(mt * 16 * 144 + k0 * 4));
                uint32_t bf[4][2];
                #pragma unroll
                for (int nt = 0; nt < 4; ++nt) {
                    const int col = wn + nt * 8 + fr;
                    bf[nt][0] = Yp[(kbase + k0 + fq) * 68 + col];
                    bf[nt][1] = Yp[(kbase + k0 + fq + 4) * 68 + col];
                }
                #pragma unroll
                for (int mt = 0; mt < 4; ++mt)
                    #pragma unroll
                    for (int nt = 0; nt < 4; ++nt)
                        mma_tf32(acc[mt][nt], a[mt], bf[nt]);
            }
        }

        asm volatile("cp.async.wait_group 0;" ::: "memory");
        __syncthreads();
    }

    // ---- epilogue: ReLU + store (D fragment layout) ----
    const int g2 = lane >> 2, cq = lane & 3;
    #pragma unroll
    for (int mt = 0; mt < 4; ++mt) {
        const int o0 = wm + mt * 16 + g2;
        #pragma unroll
        for (int nt = 0; nt < 4; ++nt) {
            const int nn0 = half * 64 + wn + nt * 8 + cq * 2;
            float* p = out + (((long)(b * 256 + o0)) * HH + h) * WW + nn0;
            float2 v0, v1;
            v0.x = fmaxf(acc[mt][nt][0], 0.f);
            v0.y = fmaxf(acc[mt][nt][1], 0.f);
            v1.x = fmaxf(acc[mt][nt][2], 0.f);
            v1.y = fmaxf(acc[mt][nt][3], 0.f);
            *(float2*)p = v0;
            *(float2*)(p + 8L * HH * WW) = v1;
        }
    }
}

// ================= launch =================
extern "C" void kernel_launch(void* const* d_in, const int* in_sizes, int n_in,
                              void* d_out, int out_size)
{
    const float* x     = (const float*)d_in[0];
    const float* wh1   = (const float*)d_in[1];
    const float* wh2   = (const float*)d_in[2];
    const float* wv1   = (const float*)d_in[3];
    const float* wv2   = (const float*)d_in[4];
    const float* wproj = (const float*)d_in[5];
    float* out = (float*)d_out;

    se_prep<<<1024, 256>>>(wproj, wh1, wh2, wv1, wv2);

    cudaFuncSetAttribute(se_main, cudaFuncAttributeMaxDynamicSharedMemorySize, SMEM_BYTES);
    dim3 grid(2, HH, BB);
    se_main<<<grid, 256, SMEM_BYTES>>>(x, out);
}